// round 4
// baseline (speedup 1.0000x reference)
#include <cuda_runtime.h>

// NAM_42442866819214 — 2 kernels + PDL, max-parallelism streaming phase.
//
// Collapse (per-feature, valid when b1[f,:]==0 && b2[f,:]==0, verified at
// runtime into g_mode[f]):
//   relu(x*w) = x * (x>0 ? max(w,0) : min(w,0))
//   contrib(b,f) = x * (x>0 ? dpos[f] : dneg[f]) + b3[f]
//
// nam_pre : 128 blocks x 128 thr (4 warps split the H1 loop), folds
//           W1,W2,W3 -> dpos/dneg. Triggers PDL at entry.
// nam_main: 1024 blocks x 256 thr, ONE WARP PER BATCH ROW (8192 warps),
//           each thread 1 float4 in / 1 float4 out; input prefetched
//           before cudaGridDependencySynchronize().

#define NB   8192
#define NF   128
#define NH1  64
#define NH2  32

__device__ float g_dpos[NF];
__device__ float g_dneg[NF];
__device__ int   g_mode[NF];   // 0 = fast path valid (rewritten every launch)

// ---------------------------------------------------------------- precompute
__global__ void __launch_bounds__(128)
nam_pre(const float* __restrict__ W1,
        const float* __restrict__ b1,
        const float* __restrict__ W2,
        const float* __restrict__ b2,
        const float* __restrict__ W3) {
    cudaTriggerProgrammaticLaunchCompletion();

    const int f    = blockIdx.x;
    const int lane = threadIdx.x & 31;   // H2 unit k
    const int warp = threadIdx.x >> 5;   // i-range chunk, 0..3
    const int k    = lane;

    // bias check: 64 b1 + 32 b2 entries, spread over 96 of 128 threads
    int nz = 0;
    if (threadIdx.x < NH1)            nz |= (b1[f * NH1 + threadIdx.x] != 0.f);
    else if (threadIdx.x < NH1 + NH2) nz |= (b2[f * NH2 + threadIdx.x - NH1] != 0.f);

    float cp = 0.f, cn = 0.f;
#pragma unroll
    for (int j = 0; j < 16; j++) {
        const int i = warp * 16 + j;
        float w  = W1[f * NH1 + i];               // warp-uniform
        float w2 = W2[(f * NH1 + i) * NH2 + k];   // coalesced
        cp = fmaf(w2, fmaxf(w, 0.f), cp);
        cn = fmaf(w2, fminf(w, 0.f), cn);
    }

    __shared__ float s_cp[4][32], s_cn[4][32];
    __shared__ int   s_nz[4];
    s_cp[warp][k] = cp;
    s_cn[warp][k] = cn;
    int wnz = __ballot_sync(0xffffffffu, nz) ? 1 : 0;
    if (lane == 0) s_nz[warp] = wnz;
    __syncthreads();

    if (warp == 0) {
        float tcp = s_cp[0][k] + s_cp[1][k] + s_cp[2][k] + s_cp[3][k];
        float tcn = s_cn[0][k] + s_cn[1][k] + s_cn[2][k] + s_cn[3][k];
        float w3  = W3[f * NH2 + k];
        float dp  = w3 * fmaxf(tcp, 0.f);   // x>0: relu(x*cp) = x*max(cp,0)
        float dn  = w3 * fminf(tcn, 0.f);   // x<0: relu(x*cn) = x*min(cn,0)
#pragma unroll
        for (int o = 16; o > 0; o >>= 1) {
            dp += __shfl_xor_sync(0xffffffffu, dp, o);
            dn += __shfl_xor_sync(0xffffffffu, dn, o);
        }
        if (k == 0) {
            g_dpos[f] = dp;
            g_dneg[f] = dn;
            g_mode[f] = (s_nz[0] | s_nz[1] | s_nz[2] | s_nz[3]);
        }
    }
}

// ------------------------------------------------------------------ fallback
__device__ __noinline__ float mlp_full(float x, int f,
                                       const float* __restrict__ W1,
                                       const float* __restrict__ b1,
                                       const float* __restrict__ W2,
                                       const float* __restrict__ b2,
                                       const float* __restrict__ W3) {
    float acc = 0.f;
    for (int k = 0; k < NH2; k++) {
        float a = b2[f * NH2 + k];
        for (int i = 0; i < NH1; i++) {
            float h1 = fmaxf(fmaf(x, W1[f * NH1 + i], b1[f * NH1 + i]), 0.f);
            a = fmaf(h1, W2[(f * NH1 + i) * NH2 + k], a);
        }
        acc = fmaf(fmaxf(a, 0.f), W3[f * NH2 + k], acc);
    }
    return acc;
}

// ---------------------------------------------------------------------- main
// grid = 1024, block = 256 (8 warps). Warp w of block B owns row b = B*8+w.
__global__ void __launch_bounds__(256)
nam_main(const float* __restrict__ inputs,
         const float* __restrict__ W1,
         const float* __restrict__ b1,
         const float* __restrict__ W2,
         const float* __restrict__ b2,
         const float* __restrict__ W3,
         const float* __restrict__ b3,
         const float* __restrict__ bias,
         float* __restrict__ out) {
    const int lane = threadIdx.x & 31;
    const int warp = threadIdx.x >> 5;
    const int b    = blockIdx.x * 8 + warp;   // batch row
    const int f0   = lane * 4;

    // ---- prefetch (independent of nam_pre) -------------------------------
    const float4 x = ((const float4*)inputs)[b * (NF / 4) + lane];

    // ---- wait for nam_pre ------------------------------------------------
    cudaGridDependencySynchronize();

    const float4 dp4 = ((const float4*)g_dpos)[lane];
    const float4 dn4 = ((const float4*)g_dneg)[lane];
    const int4   m4  = ((const int4*)g_mode)[lane];
    const float4 b34 = ((const float4*)b3)[lane];
    const bool fast = (m4.x | m4.y | m4.z | m4.w) == 0;

    float4 c;
    if (fast) {
        c.x = fmaf(x.x, (x.x > 0.f ? dp4.x : dn4.x), b34.x);
        c.y = fmaf(x.y, (x.y > 0.f ? dp4.y : dn4.y), b34.y);
        c.z = fmaf(x.z, (x.z > 0.f ? dp4.z : dn4.z), b34.z);
        c.w = fmaf(x.w, (x.w > 0.f ? dp4.w : dn4.w), b34.w);
    } else {
        c.x = mlp_full(x.x, f0 + 0, W1, b1, W2, b2, W3) + b34.x;
        c.y = mlp_full(x.y, f0 + 1, W1, b1, W2, b2, W3) + b34.y;
        c.z = mlp_full(x.z, f0 + 2, W1, b1, W2, b2, W3) + b34.z;
        c.w = mlp_full(x.w, f0 + 3, W1, b1, W2, b2, W3) + b34.w;
    }
    ((float4*)(out + NB))[b * (NF / 4) + lane] = c;

    float s = (c.x + c.y) + (c.z + c.w);
#pragma unroll
    for (int o = 16; o > 0; o >>= 1)
        s += __shfl_xor_sync(0xffffffffu, s, o);
    if (lane == 0) out[b] = s + bias[0];
}

// -------------------------------------------------------------------- launch
extern "C" void kernel_launch(void* const* d_in, const int* in_sizes, int n_in,
                              void* d_out, int out_size) {
    const float* inputs = (const float*)d_in[0];
    const float* W1     = (const float*)d_in[1];
    const float* b1     = (const float*)d_in[2];
    const float* W2     = (const float*)d_in[3];
    const float* b2     = (const float*)d_in[4];
    const float* W3     = (const float*)d_in[5];
    const float* b3     = (const float*)d_in[6];
    const float* bias   = (const float*)d_in[7];
    float* out = (float*)d_out;

    nam_pre<<<NF, 128>>>(W1, b1, W2, b2, W3);

    cudaLaunchConfig_t cfg = {};
    cfg.gridDim  = dim3(NB / 8, 1, 1);
    cfg.blockDim = dim3(256, 1, 1);
    cfg.dynamicSmemBytes = 0;
    cfg.stream = 0;
    cudaLaunchAttribute attr[1];
    attr[0].id = cudaLaunchAttributeProgrammaticStreamSerialization;
    attr[0].val.programmaticStreamSerializationAllowed = 1;
    cfg.attrs = attr;
    cfg.numAttrs = 1;
    cudaLaunchKernelEx(&cfg, nam_main,
                       inputs, W1, b1, W2, b2, W3, b3, bias, out);
}

// round 5
// speedup vs baseline: 1.2000x; 1.2000x over previous
#include <cuda_runtime.h>

// NAM_42442866819214 — 2 kernels + PDL.
//
// Collapse (per-feature, valid when b1[f,:]==0 && b2[f,:]==0, verified at
// runtime into g_mode[f]):
//   relu(x*w) = x * (x>0 ? max(w,0) : min(w,0))
//   contrib(b,f) = x * (x>0 ? dpos[f] : dneg[f]) + b3[f]
//
// nam_pre : folds W1,W2,W3 -> dpos/dneg (128 blocks x 128 thr), PDL-triggers
//           at entry so nam_main overlaps it.
// nam_main: grid 256 x 256 thr — ALL blocks wave-1 resident (4/SM at <=64
//           regs), one warp per 4 rows. Everything independent of nam_pre
//           (inputs, b3, bias) is prefetched BEFORE
//           cudaGridDependencySynchronize(); only the 1.5KB of folded
//           coefficients is read after.

#define NB   8192
#define NF   128
#define NH1  64
#define NH2  32
#define GRID 256
#define RPB  32   // rows per block = 8 warps * 4 rows

__device__ float g_dpos[NF];
__device__ float g_dneg[NF];
__device__ int   g_mode[NF];   // 0 = fast path valid (rewritten every launch)

// ---------------------------------------------------------------- precompute
__global__ void __launch_bounds__(128)
nam_pre(const float* __restrict__ W1,
        const float* __restrict__ b1,
        const float* __restrict__ W2,
        const float* __restrict__ b2,
        const float* __restrict__ W3) {
    cudaTriggerProgrammaticLaunchCompletion();

    const int f    = blockIdx.x;
    const int lane = threadIdx.x & 31;   // H2 unit k
    const int warp = threadIdx.x >> 5;   // i-chunk 0..3
    const int k    = lane;

    int nz = 0;
    if (threadIdx.x < NH1)            nz |= (b1[f * NH1 + threadIdx.x] != 0.f);
    else if (threadIdx.x < NH1 + NH2) nz |= (b2[f * NH2 + threadIdx.x - NH1] != 0.f);

    float cp = 0.f, cn = 0.f;
#pragma unroll
    for (int j = 0; j < 16; j++) {
        const int i = warp * 16 + j;
        float w  = W1[f * NH1 + i];               // warp-uniform
        float w2 = W2[(f * NH1 + i) * NH2 + k];   // coalesced
        cp = fmaf(w2, fmaxf(w, 0.f), cp);
        cn = fmaf(w2, fminf(w, 0.f), cn);
    }

    __shared__ float s_cp[4][32], s_cn[4][32];
    __shared__ int   s_nz[4];
    s_cp[warp][k] = cp;
    s_cn[warp][k] = cn;
    int wnz = __ballot_sync(0xffffffffu, nz) ? 1 : 0;
    if (lane == 0) s_nz[warp] = wnz;
    __syncthreads();

    if (warp == 0) {
        float tcp = s_cp[0][k] + s_cp[1][k] + s_cp[2][k] + s_cp[3][k];
        float tcn = s_cn[0][k] + s_cn[1][k] + s_cn[2][k] + s_cn[3][k];
        float w3  = W3[f * NH2 + k];
        float dp  = w3 * fmaxf(tcp, 0.f);
        float dn  = w3 * fminf(tcn, 0.f);
#pragma unroll
        for (int o = 16; o > 0; o >>= 1) {
            dp += __shfl_xor_sync(0xffffffffu, dp, o);
            dn += __shfl_xor_sync(0xffffffffu, dn, o);
        }
        if (k == 0) {
            g_dpos[f] = dp;
            g_dneg[f] = dn;
            g_mode[f] = (s_nz[0] | s_nz[1] | s_nz[2] | s_nz[3]);
        }
    }
}

// ------------------------------------------------------------------ fallback
// Dead unless b1/b2 nonzero; launch bounds force it to spill, keeping the
// fast path's register budget small.
__device__ __noinline__ float mlp_full(float x, int f,
                                       const float* __restrict__ W1,
                                       const float* __restrict__ b1,
                                       const float* __restrict__ W2,
                                       const float* __restrict__ b2,
                                       const float* __restrict__ W3) {
    float acc = 0.f;
    for (int k = 0; k < NH2; k++) {
        float a = b2[f * NH2 + k];
        for (int i = 0; i < NH1; i++) {
            float h1 = fmaxf(fmaf(x, W1[f * NH1 + i], b1[f * NH1 + i]), 0.f);
            a = fmaf(h1, W2[(f * NH1 + i) * NH2 + k], a);
        }
        acc = fmaf(fmaxf(a, 0.f), W3[f * NH2 + k], acc);
    }
    return acc;
}

// ---------------------------------------------------------------------- main
// grid 256 x 256. Warp w of block B owns rows {B*32 + r*8 + w : r=0..3}.
__global__ void __launch_bounds__(256, 4)
nam_main(const float* __restrict__ inputs,
         const float* __restrict__ W1,
         const float* __restrict__ b1,
         const float* __restrict__ W2,
         const float* __restrict__ b2,
         const float* __restrict__ W3,
         const float* __restrict__ b3,
         const float* __restrict__ bias,
         float* __restrict__ out) {
    const int lane = threadIdx.x & 31;
    const int warp = threadIdx.x >> 5;   // 0..7
    const int b0   = blockIdx.x * RPB + warp;
    const int f0   = lane * 4;

    const float4* in4 = (const float4*)inputs;
    float4*       c4  = (float4*)(out + NB);

    // ---- prefetch everything independent of nam_pre ----------------------
    float4 x[4];
#pragma unroll
    for (int r = 0; r < 4; r++)
        x[r] = in4[(b0 + r * 8) * (NF / 4) + lane];
    const float4 b34   = ((const float4*)b3)[lane];
    const float  bias0 = bias[0];

    // ---- wait for nam_pre -------------------------------------------------
    cudaGridDependencySynchronize();

    const float4 dp4 = ((const float4*)g_dpos)[lane];
    const float4 dn4 = ((const float4*)g_dneg)[lane];
    const int4   m4  = ((const int4*)g_mode)[lane];
    const bool fast = (m4.x | m4.y | m4.z | m4.w) == 0;

#pragma unroll
    for (int r = 0; r < 4; r++) {
        const int b = b0 + r * 8;
        float4 c;
        if (fast) {
            c.x = fmaf(x[r].x, (x[r].x > 0.f ? dp4.x : dn4.x), b34.x);
            c.y = fmaf(x[r].y, (x[r].y > 0.f ? dp4.y : dn4.y), b34.y);
            c.z = fmaf(x[r].z, (x[r].z > 0.f ? dp4.z : dn4.z), b34.z);
            c.w = fmaf(x[r].w, (x[r].w > 0.f ? dp4.w : dn4.w), b34.w);
        } else {
            c.x = mlp_full(x[r].x, f0 + 0, W1, b1, W2, b2, W3) + b34.x;
            c.y = mlp_full(x[r].y, f0 + 1, W1, b1, W2, b2, W3) + b34.y;
            c.z = mlp_full(x[r].z, f0 + 2, W1, b1, W2, b2, W3) + b34.z;
            c.w = mlp_full(x[r].w, f0 + 3, W1, b1, W2, b2, W3) + b34.w;
        }
        c4[b * (NF / 4) + lane] = c;

        float s = (c.x + c.y) + (c.z + c.w);
#pragma unroll
        for (int o = 16; o > 0; o >>= 1)
            s += __shfl_xor_sync(0xffffffffu, s, o);
        if (lane == 0) out[b] = s + bias0;
    }
}

// -------------------------------------------------------------------- launch
extern "C" void kernel_launch(void* const* d_in, const int* in_sizes, int n_in,
                              void* d_out, int out_size) {
    const float* inputs = (const float*)d_in[0];
    const float* W1     = (const float*)d_in[1];
    const float* b1     = (const float*)d_in[2];
    const float* W2     = (const float*)d_in[3];
    const float* b2     = (const float*)d_in[4];
    const float* W3     = (const float*)d_in[5];
    const float* b3     = (const float*)d_in[6];
    const float* bias   = (const float*)d_in[7];
    float* out = (float*)d_out;

    nam_pre<<<NF, 128>>>(W1, b1, W2, b2, W3);

    cudaLaunchConfig_t cfg = {};
    cfg.gridDim  = dim3(GRID, 1, 1);
    cfg.blockDim = dim3(256, 1, 1);
    cfg.dynamicSmemBytes = 0;
    cfg.stream = 0;
    cudaLaunchAttribute attr[1];
    attr[0].id = cudaLaunchAttributeProgrammaticStreamSerialization;
    attr[0].val.programmaticStreamSerializationAllowed = 1;
    cfg.attrs = attr;
    cfg.numAttrs = 1;
    cudaLaunchKernelEx(&cfg, nam_main,
                       inputs, W1, b1, W2, b2, W3, b3, bias, out);
}